// round 4
// baseline (speedup 1.0000x reference)
#include <cuda_runtime.h>
#include <math.h>

#define POOLED   7
#define CHANNELS 256
#define BATCH    4
#define H        50
#define W        50
#define HW       (H*W)
#define SCALE    0.0625f

// NHWC scratch: featT[b][h][w][c]
__device__ float g_featT[(size_t)BATCH * HW * CHANNELS];

// ---------------- Transpose NCHW -> NHWC (tiled, conflict-free) -------------
// Treat per-batch as 2D transpose of [C=256][HW=2500].
__global__ void __launch_bounds__(256)
transpose_kernel(const float* __restrict__ feat)
{
    __shared__ float tile[32][33];

    int b       = blockIdx.z;
    int hw0     = blockIdx.x * 32;
    int c0      = blockIdx.y * 32;
    int tx      = threadIdx.x;         // 0..31
    int ty      = threadIdx.y;         // 0..7

    const float* in = feat + (size_t)b * CHANNELS * HW;

    #pragma unroll
    for (int i = 0; i < 32; i += 8) {
        int c  = c0 + ty + i;
        int hw = hw0 + tx;
        if (hw < HW)  // c always < 256 (256 % 32 == 0)
            tile[ty + i][tx] = in[(size_t)c * HW + hw];
    }
    __syncthreads();

    float* outp = g_featT + (size_t)b * HW * CHANNELS;
    #pragma unroll
    for (int i = 0; i < 32; i += 8) {
        int hw = hw0 + ty + i;
        int c  = c0 + tx;
        if (hw < HW)
            outp[(size_t)hw * CHANNELS + c] = tile[tx][ty + i];
    }
}

// ---------------- RoI max-pool over NHWC, lane = channel --------------------
// One block (64 threads) per (roi, bin). Thread t handles channels 4t..4t+3.
__global__ void __launch_bounds__(64)
roipool_nhwc_kernel(const float* __restrict__ rois,
                    float* __restrict__ out)
{
    int blk = blockIdx.x;          // r*49 + bin
    int r   = blk / 49;
    int bin = blk - r * 49;
    int ph  = bin / POOLED;
    int pw  = bin - ph * POOLED;

    const float* roi = rois + r * 5;
    int   b  = (int)roi[0];
    float x1 = floorf(__fadd_rn(__fmul_rn(roi[1], SCALE), 0.5f));
    float y1 = floorf(__fadd_rn(__fmul_rn(roi[2], SCALE), 0.5f));
    float x2 = floorf(__fadd_rn(__fmul_rn(roi[3], SCALE), 0.5f));
    float y2 = floorf(__fadd_rn(__fmul_rn(roi[4], SCALE), 0.5f));

    float roi_w = fmaxf(__fadd_rn(__fadd_rn(x2, -x1), 1.0f), 1.0f);
    float roi_h = fmaxf(__fadd_rn(__fadd_rn(y2, -y1), 1.0f), 1.0f);

    // Match XLA-CPU fast-math: x/7 lowered to x * fl32(1/7)
    const float inv7 = 1.0f / 7.0f;
    float bin_w = __fmul_rn(roi_w, inv7);
    float bin_h = __fmul_rn(roi_h, inv7);

    float pwf = (float)pw;
    float phf = (float)ph;

    float ws = fminf(fmaxf(__fadd_rn(floorf(__fmul_rn(pwf, bin_w)), x1), 0.0f), (float)W);
    float we = fminf(fmaxf(__fadd_rn(ceilf(__fmul_rn(__fadd_rn(pwf, 1.0f), bin_w)), x1), 0.0f), (float)W);
    float hs = fminf(fmaxf(__fadd_rn(floorf(__fmul_rn(phf, bin_h)), y1), 0.0f), (float)H);
    float he = fminf(fmaxf(__fadd_rn(ceilf(__fmul_rn(__fadd_rn(phf, 1.0f), bin_h)), y1), 0.0f), (float)H);

    int iws = (int)ws, iwe = (int)we;
    int ihs = (int)hs, ihe = (int)he;

    int t = threadIdx.x;                 // 0..63, channels 4t..4t+3
    int c = t << 2;

    // out layout: ((r*256 + c)*49 + bin)
    float* o = out + ((size_t)r * CHANNELS + c) * 49 + bin;

    if (ihe <= ihs || iwe <= iws) {
        o[0]      = 0.0f;
        o[49]     = 0.0f;
        o[98]     = 0.0f;
        o[147]    = 0.0f;
        return;
    }

    const float4* base = (const float4*)(g_featT + (size_t)b * HW * CHANNELS);
    // element index: (h*W + w)*64 + t   (in float4 units, 64 float4 per pixel)

    float4 m = make_float4(-INFINITY, -INFINITY, -INFINITY, -INFINITY);
    for (int h = ihs; h < ihe; ++h) {
        const float4* rowp = base + (size_t)(h * W) * 64 + t;
        for (int w = iws; w < iwe; ++w) {
            float4 v = __ldg(rowp + (size_t)w * 64);
            m.x = fmaxf(m.x, v.x);
            m.y = fmaxf(m.y, v.y);
            m.z = fmaxf(m.z, v.z);
            m.w = fmaxf(m.w, v.w);
        }
    }
    o[0]   = m.x;
    o[49]  = m.y;
    o[98]  = m.z;
    o[147] = m.w;
}

extern "C" void kernel_launch(void* const* d_in, const int* in_sizes, int n_in,
                              void* d_out, int out_size)
{
    const float* feat = (const float*)d_in[0];
    const float* rois = (const float*)d_in[1];
    float* out = (float*)d_out;

    dim3 tgrid((HW + 31) / 32, CHANNELS / 32, BATCH);   // 79 x 8 x 4
    dim3 tblk(32, 8);
    transpose_kernel<<<tgrid, tblk>>>(feat);

    int blocks = 128 * 49;   // (roi, bin)
    roipool_nhwc_kernel<<<blocks, 64>>>(rois, out);
}